// round 3
// baseline (speedup 1.0000x reference)
#include <cuda_runtime.h>
#include <math.h>

#define NNODE 1024
#define BNROWS 32768
#define EPS_F 1e-6f

#define OFF_H    ((size_t)0)
#define OFF_T0   (OFF_H   + 4194304)
#define OFF_M    (OFF_T0  + 4194304)
#define OFF_SUM  (OFF_M   + 4194304)
#define OFF_CNT  (OFF_SUM + 4194304)
#define OFF_HC   (OFF_CNT + 32768)
#define OFF_Q2   (OFF_HC  + 8388608)
#define OFF_K2   (OFF_Q2  + 4194304)
#define OFF_V2   (OFF_K2  + 1048576)
#define OFF_OH   (OFF_V2  + 1048576)
#define OFF_HNUM (OFF_OH  + 4194304)
#define OFF_WQF  (OFF_HNUM + 4096)
#define OFF_BQF  (OFF_WQF + 32768)
#define OFF_WKF  (OFF_BQF + 128)
#define OFF_BKF  (OFF_WKF + 32768)
#define OFF_WVF  (OFF_BKF + 128)
#define OFF_BVF  (OFF_WVF + 32768)
#define SCRATCH_FLOATS (OFF_BVF + 128)

__device__ float g_scratch[SCRATCH_FLOATS];

__device__ __forceinline__ float ftanh(float x) {
    float t = __expf(2.0f * x);
    return 1.0f - __fdividef(2.0f, t + 1.0f);
}

// h_num = tanh(tanh(num@W0+b0)@W1+b1)
__global__ void k_hnum(const float* __restrict__ num, const float* __restrict__ W0,
                       const float* __restrict__ b0, const float* __restrict__ W1,
                       const float* __restrict__ b1, float* __restrict__ out) {
    __shared__ float xs[64];
    __shared__ float hid[256];
    int b = blockIdx.x, t = threadIdx.x;
    if (t < 64) xs[t] = num[b * 64 + t];
    __syncthreads();
    float a = b0[t];
    #pragma unroll 8
    for (int k = 0; k < 64; k++) a += xs[k] * W0[k * 256 + t];
    hid[t] = ftanh(a);
    __syncthreads();
    if (t < 128) {
        float a2 = b1[t];
        #pragma unroll 8
        for (int k = 0; k < 256; k++) a2 += hid[k] * W1[k * 128 + t];
        out[b * 128 + t] = ftanh(a2);
    }
}

// h = tanh(nf@Wn+bn) + pos
__global__ void __launch_bounds__(128) k_embed(const float* __restrict__ nf,
        const float* __restrict__ Wn, const float* __restrict__ bn,
        const float* __restrict__ pos, float* __restrict__ h) {
    __shared__ float ws[4096];
    __shared__ float xs[256];
    int t = threadIdx.x;
    int rbase = blockIdx.x * 8;
    for (int i = t; i < 4096; i += 128) ws[i] = Wn[i];
    for (int i = t; i < 256; i += 128) xs[i] = nf[(size_t)rbase * 32 + i];
    __syncthreads();
    float bv = bn[t];
    #pragma unroll
    for (int r = 0; r < 8; r++) {
        float a = bv;
        #pragma unroll 8
        for (int k = 0; k < 32; k++) a += xs[r * 32 + k] * ws[k * 128 + t];
        int row = rbase + r;
        h[(size_t)row * 128 + t] = ftanh(a) + pos[(size_t)(row & 1023) * 128 + t];
    }
}

// Y[M,128] = act(X@W + b); row r -> batch r/rpb, node map(r%rpb)
__global__ void __launch_bounds__(256) gemm_k(
    const float* __restrict__ X, int ldx, int rpb, size_t bstride,
    const int* __restrict__ rowmap,
    const float* __restrict__ W, const float* __restrict__ bias,
    float* __restrict__ Y, int ldy, int K, int do_tanh) {
    __shared__ float Xs[64][33];
    __shared__ float Ws[32][128];
    __shared__ unsigned long long rowoff[64];
    int tid = threadIdx.x;
    int rbase = blockIdx.x * 64;
    if (tid < 64) {
        int r = rbase + tid;
        int bb = r / rpb;
        int n = r - bb * rpb;
        if (rowmap) n = rowmap[n];
        rowoff[tid] = (size_t)bb * bstride + (size_t)n * ldx;
    }
    __syncthreads();
    float acc[4][8];
    #pragma unroll
    for (int i = 0; i < 4; i++)
        #pragma unroll
        for (int j = 0; j < 8; j++) acc[i][j] = 0.0f;
    int rg = tid >> 4, cg = tid & 15;
    int r0 = rg * 4, c0 = cg * 8;
    for (int kb = 0; kb < K; kb += 32) {
        #pragma unroll
        for (int p = 0; p < 8; p++) {
            int idx = p * 256 + tid;
            int m = idx >> 5, k = idx & 31;
            Xs[m][k] = X[rowoff[m] + kb + k];
        }
        #pragma unroll
        for (int p = 0; p < 16; p++) {
            int idx = p * 256 + tid;
            int kk = idx >> 7, col = idx & 127;
            Ws[kk][col] = W[(size_t)(kb + kk) * 128 + col];
        }
        __syncthreads();
        #pragma unroll
        for (int k = 0; k < 32; k++) {
            float xv[4];
            xv[0] = Xs[r0][k]; xv[1] = Xs[r0 + 1][k];
            xv[2] = Xs[r0 + 2][k]; xv[3] = Xs[r0 + 3][k];
            float4 wa = *(const float4*)&Ws[k][c0];
            float4 wb = *(const float4*)&Ws[k][c0 + 4];
            float wv[8] = {wa.x, wa.y, wa.z, wa.w, wb.x, wb.y, wb.z, wb.w};
            #pragma unroll
            for (int i = 0; i < 4; i++)
                #pragma unroll
                for (int j = 0; j < 8; j++) acc[i][j] += xv[i] * wv[j];
        }
        __syncthreads();
    }
    float bv[8];
    #pragma unroll
    for (int j = 0; j < 8; j++) bv[j] = bias[c0 + j];
    #pragma unroll
    for (int i = 0; i < 4; i++) {
        float o[8];
        #pragma unroll
        for (int j = 0; j < 8; j++) {
            o[j] = acc[i][j] + bv[j];
            if (do_tanh) o[j] = ftanh(o[j]);
        }
        size_t yoff = (size_t)(rbase + r0 + i) * ldy + c0;
        *(float4*)(Y + yoff)     = make_float4(o[0], o[1], o[2], o[3]);
        *(float4*)(Y + yoff + 4) = make_float4(o[4], o[5], o[6], o[7]);
    }
}

__global__ void k_zero(float* __restrict__ sum, float* __restrict__ cnt) {
    int stride = gridDim.x * blockDim.x;
    int t0 = blockIdx.x * blockDim.x + threadIdx.x;
    for (int i = t0; i < BNROWS * 32; i += stride)
        ((float4*)sum)[i] = make_float4(0.f, 0.f, 0.f, 0.f);
    for (int i = t0; i < BNROWS; i += stride) cnt[i] = 0.f;
}

// one warp per edge: sum[src]+=m[dst], sum[dst]+=m[src], cnt++
__global__ void __launch_bounds__(256) k_scatter(const int* __restrict__ eidx,
        const float* __restrict__ m, float* __restrict__ sum, float* __restrict__ cnt) {
    int gw = (blockIdx.x * 256 + threadIdx.x) >> 5;
    int lane = threadIdx.x & 31;
    int b = gw >> 14;
    int2 ab = __ldg((const int2*)eidx + gw);
    size_t basea = ((size_t)b * NNODE + ab.x) * 128;
    size_t baseb = ((size_t)b * NNODE + ab.y) * 128;
    float4 va = *(const float4*)(m + basea + lane * 4);
    float4 vb = *(const float4*)(m + baseb + lane * 4);
    float* da = sum + basea + lane * 4;
    float* db = sum + baseb + lane * 4;
    atomicAdd(da + 0, vb.x); atomicAdd(da + 1, vb.y);
    atomicAdd(da + 2, vb.z); atomicAdd(da + 3, vb.w);
    atomicAdd(db + 0, va.x); atomicAdd(db + 1, va.y);
    atomicAdd(db + 2, va.z); atomicAdd(db + 3, va.w);
    if (lane == 0)      atomicAdd(cnt + b * NNODE + ab.x, 1.0f);
    else if (lane == 1) atomicAdd(cnt + b * NNODE + ab.y, 1.0f);
}

// fused: comb=[h, sum*rcp]; gate=tanh(comb@Wg+bg); upd=tanh(comb@Wu+bu); out=g*u+(1-g)*h
__global__ void __launch_bounds__(256) k_gate(const float* __restrict__ h,
        const float* __restrict__ sum, const float* __restrict__ cnt,
        const float* __restrict__ Wg, const float* __restrict__ bg,
        const float* __restrict__ Wu, const float* __restrict__ bu,
        float* __restrict__ out) {
    __shared__ float Xs[64][33];
    __shared__ float Wgs[32][128];
    __shared__ float Wus[32][128];
    __shared__ float rcps[64];
    int tid = threadIdx.x;
    int rbase = blockIdx.x * 64;
    if (tid < 64) rcps[tid] = __fdividef(1.0f, cnt[rbase + tid] + EPS_F);
    __syncthreads();
    float ag[4][8], au[4][8];
    #pragma unroll
    for (int i = 0; i < 4; i++)
        #pragma unroll
        for (int j = 0; j < 8; j++) { ag[i][j] = 0.f; au[i][j] = 0.f; }
    int rg = tid >> 4, cg = tid & 15;
    int r0 = rg * 4, c0 = cg * 8;
    for (int kb = 0; kb < 256; kb += 32) {
        #pragma unroll
        for (int p = 0; p < 8; p++) {
            int idx = p * 256 + tid;
            int m = idx >> 5, k = idx & 31;
            int kk = kb + k;
            float v;
            if (kk < 128) v = h[(size_t)(rbase + m) * 128 + kk];
            else v = sum[(size_t)(rbase + m) * 128 + kk - 128] * rcps[m];
            Xs[m][k] = v;
        }
        #pragma unroll
        for (int p = 0; p < 16; p++) {
            int idx = p * 256 + tid;
            int kk = idx >> 7, col = idx & 127;
            Wgs[kk][col] = Wg[(size_t)(kb + kk) * 128 + col];
            Wus[kk][col] = Wu[(size_t)(kb + kk) * 128 + col];
        }
        __syncthreads();
        #pragma unroll
        for (int k = 0; k < 32; k++) {
            float xv[4];
            xv[0] = Xs[r0][k]; xv[1] = Xs[r0 + 1][k];
            xv[2] = Xs[r0 + 2][k]; xv[3] = Xs[r0 + 3][k];
            float4 ga = *(const float4*)&Wgs[k][c0];
            float4 gb = *(const float4*)&Wgs[k][c0 + 4];
            float4 ua = *(const float4*)&Wus[k][c0];
            float4 ub = *(const float4*)&Wus[k][c0 + 4];
            float gv[8] = {ga.x, ga.y, ga.z, ga.w, gb.x, gb.y, gb.z, gb.w};
            float uv[8] = {ua.x, ua.y, ua.z, ua.w, ub.x, ub.y, ub.z, ub.w};
            #pragma unroll
            for (int i = 0; i < 4; i++)
                #pragma unroll
                for (int j = 0; j < 8; j++) {
                    ag[i][j] += xv[i] * gv[j];
                    au[i][j] += xv[i] * uv[j];
                }
        }
        __syncthreads();
    }
    #pragma unroll
    for (int i = 0; i < 4; i++) {
        int row = rbase + r0 + i;
        float4 ha = *(const float4*)(h + (size_t)row * 128 + c0);
        float4 hb = *(const float4*)(h + (size_t)row * 128 + c0 + 4);
        float hv[8] = {ha.x, ha.y, ha.z, ha.w, hb.x, hb.y, hb.z, hb.w};
        float o[8];
        #pragma unroll
        for (int j = 0; j < 8; j++) {
            float g = ftanh(ag[i][j] + bg[c0 + j]);
            float u = ftanh(au[i][j] + bu[c0 + j]);
            o[j] = g * u + (1.0f - g) * hv[j];
        }
        size_t yoff = (size_t)row * 256 + c0;
        *(float4*)(out + yoff)     = make_float4(o[0], o[1], o[2], o[3]);
        *(float4*)(out + yoff + 4) = make_float4(o[4], o[5], o[6], o[7]);
    }
}

// fold W_in into Wq1/Wk1/Wv1 (and biases)
__global__ void k_fuseW(const float* __restrict__ Wq1, const float* __restrict__ bq1,
                        const float* __restrict__ Wk1, const float* __restrict__ bk1,
                        const float* __restrict__ Wv1, const float* __restrict__ bv1,
                        const float* __restrict__ W_in, const float* __restrict__ b_in,
                        float* __restrict__ S) {
    int mat = blockIdx.y, r = blockIdx.x, c = threadIdx.x;
    const float* Wsrc = mat == 0 ? Wq1 : (mat == 1 ? Wk1 : Wv1);
    const float* bsrc = mat == 0 ? bq1 : (mat == 1 ? bk1 : bv1);
    float* Wd = S + (mat == 0 ? OFF_WQF : (mat == 1 ? OFF_WKF : OFF_WVF));
    float* bd = S + (mat == 0 ? OFF_BQF : (mat == 1 ? OFF_BKF : OFF_BVF));
    __shared__ float row[128];
    row[c] = (r < 256) ? Wsrc[r * 128 + c] : bsrc[c];
    __syncthreads();
    float a = 0.f;
    #pragma unroll 8
    for (int k = 0; k < 128; k++) a += row[k] * W_in[k * 384 + mat * 128 + c];
    if (r < 256) Wd[r * 128 + c] = a;
    else bd[c] = a + b_in[mat * 128 + c];
}

// attention: block = (head, batch); warp per query; K/V head-slices in smem
__global__ void __launch_bounds__(512) k_attn(const float* __restrict__ q2,
        const float* __restrict__ k2, const float* __restrict__ v2,
        float* __restrict__ oh) {
    int h = blockIdx.x, b = blockIdx.y;
    __shared__ float Ks[256][17];
    __shared__ float Vs[256][17];
    int tid = threadIdx.x;
    for (int i = tid; i < 256 * 16; i += 512) {
        int k = i >> 4, d = i & 15;
        Ks[k][d] = k2[((size_t)b * 256 + k) * 128 + h * 16 + d];
        Vs[k][d] = v2[((size_t)b * 256 + k) * 128 + h * 16 + d];
    }
    __syncthreads();
    int warp = tid >> 5, lane = tid & 31;
    for (int q = warp; q < 1024; q += 16) {
        const float* qp = q2 + ((size_t)b * 1024 + q) * 128 + h * 16;
        float qv[16];
        #pragma unroll
        for (int d = 0; d < 16; d++) qv[d] = __ldg(qp + d);
        float s[8];
        #pragma unroll
        for (int j = 0; j < 8; j++) {
            int key = lane + 32 * j;
            float a = 0.f;
            #pragma unroll
            for (int d = 0; d < 16; d++) a += qv[d] * Ks[key][d];
            s[j] = a * 0.25f;
        }
        float mx = s[0];
        #pragma unroll
        for (int j = 1; j < 8; j++) mx = fmaxf(mx, s[j]);
        #pragma unroll
        for (int o = 16; o > 0; o >>= 1) mx = fmaxf(mx, __shfl_xor_sync(0xffffffffu, mx, o));
        float sm = 0.f;
        #pragma unroll
        for (int j = 0; j < 8; j++) { s[j] = __expf(s[j] - mx); sm += s[j]; }
        #pragma unroll
        for (int o = 16; o > 0; o >>= 1) sm += __shfl_xor_sync(0xffffffffu, sm, o);
        float inv = __fdividef(1.0f, sm);
        float acc[16];
        #pragma unroll
        for (int d = 0; d < 16; d++) acc[d] = 0.f;
        #pragma unroll
        for (int j = 0; j < 8; j++) {
            int key = lane + 32 * j;
            float p = s[j];
            #pragma unroll
            for (int d = 0; d < 16; d++) acc[d] += p * Vs[key][d];
        }
        #pragma unroll
        for (int d = 0; d < 16; d++) {
            #pragma unroll
            for (int o = 16; o > 0; o >>= 1) acc[d] += __shfl_xor_sync(0xffffffffu, acc[d], o);
            acc[d] *= inv;
        }
        if (lane == 0) {
            float* op = oh + ((size_t)b * 1024 + q) * 128 + h * 16;
            #pragma unroll
            for (int d = 0; d < 16; d++) op[d] = acc[d];
        }
    }
}

// state_value + mask + stage outputs
__global__ void k_final(const float* __restrict__ hnum, const float* __restrict__ hatt,
                        const float* __restrict__ stage, float* __restrict__ out) {
    int b = blockIdx.x, t = threadIdx.x;
    float* sv = out + 4194304 + (size_t)b * 258;
    if (t < 128) sv[t] = hnum[b * 128 + t];
    else if (t < 256) {
        int c = t - 128;
        const float* p = hatt + (size_t)b * 1024 * 128 + c;
        float s = 0.f;
        for (int n = 0; n < 1024; n++) s += p[(size_t)n * 128];
        sv[128 + c] = s * (1.0f / 1024.0f);
    }
    if (t < 2) {
        sv[256 + t] = stage[b * 2 + t];
        out[4235328 + b * 2 + t] = stage[b * 2 + t];
    }
    for (int i = t; i < 1024; i += 256) out[4202560 + b * 1024 + i] = 1.0f;
}

extern "C" void kernel_launch(void* const* d_in, const int* in_sizes, int n_in,
                              void* d_out, int out_size) {
    const float* numerical = (const float*)d_in[0];
    const float* node_feature = (const float*)d_in[1];
    const float* stage = (const float*)d_in[2];
    const float* W_num0 = (const float*)d_in[3];
    const float* b_num0 = (const float*)d_in[4];
    const float* W_num1 = (const float*)d_in[5];
    const float* b_num1 = (const float*)d_in[6];
    const float* W_node = (const float*)d_in[7];
    const float* b_node = (const float*)d_in[8];
    const float* pos_enc = (const float*)d_in[9];
    const float* ew1 = (const float*)d_in[10];
    const float* eb1 = (const float*)d_in[11];
    const float* ew2 = (const float*)d_in[12];
    const float* eb2 = (const float*)d_in[13];
    const float* Wg = (const float*)d_in[14];
    const float* bg = (const float*)d_in[15];
    const float* Wu = (const float*)d_in[16];
    const float* bu = (const float*)d_in[17];
    const float* Wq1 = (const float*)d_in[18];
    const float* bq1 = (const float*)d_in[19];
    const float* Wk1 = (const float*)d_in[20];
    const float* bk1 = (const float*)d_in[21];
    const float* Wv1 = (const float*)d_in[22];
    const float* bv1 = (const float*)d_in[23];
    const float* W_in = (const float*)d_in[24];
    const float* b_in = (const float*)d_in[25];
    const float* W_out = (const float*)d_in[26];
    const float* b_out = (const float*)d_in[27];
    const int* e_dis = (const int*)d_in[28];
    const int* e_od = (const int*)d_in[29];
    const int* build_idx = (const int*)d_in[31];
    float* out = (float*)d_out;

    float* S = nullptr;
    cudaGetSymbolAddress((void**)&S, g_scratch);
    float* H   = S + OFF_H;
    float* T0  = S + OFF_T0;
    float* M   = S + OFF_M;
    float* SUM = S + OFF_SUM;
    float* CNT = S + OFF_CNT;
    float* HC  = S + OFF_HC;
    float* Q2  = S + OFF_Q2;
    float* K2  = S + OFF_K2;
    float* V2  = S + OFF_V2;
    float* OH  = S + OFF_OH;
    float* HNUM = S + OFF_HNUM;

    k_hnum<<<32, 256>>>(numerical, W_num0, b_num0, W_num1, b_num1, HNUM);
    k_embed<<<4096, 128>>>(node_feature, W_node, b_node, pos_enc, H);
    k_fuseW<<<dim3(257, 3), 128>>>(Wq1, bq1, Wk1, bk1, Wv1, bv1, W_in, b_in, S);

    for (int pass = 0; pass < 2; pass++) {
        const float* ew = pass ? ew2 : ew1;
        const float* eb = pass ? eb2 : eb1;
        const int* eidx = pass ? e_od : e_dis;
        // only L_GCN layer 1 survives; per-node edge MLP (2 layers)
        gemm_k<<<512, 256>>>(H, 128, 1 << 30, 0, nullptr, ew + 2 * 16384, eb + 2 * 128, T0, 128, 128, 1);
        gemm_k<<<512, 256>>>(T0, 128, 1 << 30, 0, nullptr, ew + 3 * 16384, eb + 3 * 128, M, 128, 128, 1);
        k_zero<<<2048, 256>>>(SUM, CNT);
        k_scatter<<<65536, 256>>>(eidx, M, SUM, CNT);
        k_gate<<<512, 256>>>(H, SUM, CNT, Wg, bg, Wu, bu, HC + pass * 128);
    }

    gemm_k<<<512, 256>>>(HC, 256, 1 << 30, 0, nullptr, S + OFF_WQF, S + OFF_BQF, Q2, 128, 256, 0);
    gemm_k<<<128, 256>>>(HC, 256, 256, 262144, build_idx, S + OFF_WKF, S + OFF_BKF, K2, 128, 256, 0);
    gemm_k<<<128, 256>>>(HC, 256, 256, 262144, build_idx, S + OFF_WVF, S + OFF_BVF, V2, 128, 256, 0);
    k_attn<<<dim3(8, 32), 512>>>(Q2, K2, V2, OH);
    gemm_k<<<512, 256>>>(OH, 128, 1 << 30, 0, nullptr, W_out, b_out, out, 128, 128, 0);
    k_final<<<32, 256>>>(HNUM, out, stage, out);
}